// round 6
// baseline (speedup 1.0000x reference)
#include <cuda_runtime.h>
#include <cuda_bf16.h>
#include <cstdint>

// Problem constants (shapes fixed by the reference).
#define N_NODES 100000
#define N_FEAT  64   // both N_IN and N_OUT
#define ROWS_PER_BLOCK 64

// Scratch for h = X @ W  (25.6 MB). __device__ global => allocation-free.
__device__ float g_h[(size_t)N_NODES * N_FEAT];

// -----------------------------------------------------------------------------
// Kernel 1: h = X @ W, W column held in REGISTERS (no shared-memory stream).
// 256 threads = 4 row-groups x 64 cols. Each thread owns output column `col`,
// loads W[:,col] into regs once, then sweeps 64 rows (2 rows in flight for ILP).
// X row reads are warp-uniform -> broadcast LDG.128, L1-resident.
// FMA-pipe bound: ~22us predicted for 409.6 MFMA.
// -----------------------------------------------------------------------------
__global__ void __launch_bounds__(256, 2) gemm_xw_kernel(
    const float* __restrict__ X, const float* __restrict__ W, int n_nodes)
{
    const int col = threadIdx.x & 63;   // output column 0..63
    const int rg  = threadIdx.x >> 6;   // row group 0..3 (each warp within one rg)

    // W column -> registers (coalesced 256B per k across the 64-col group).
    float w[N_FEAT];
    #pragma unroll
    for (int k = 0; k < N_FEAT; ++k)
        w[k] = W[k * N_FEAT + col];

    const int base = blockIdx.x * ROWS_PER_BLOCK;

    #pragma unroll 1
    for (int it = 0; it < ROWS_PER_BLOCK / 8; ++it) {
        const int r0 = base + it * 8 + rg;       // this rg's two rows
        const int r1 = r0 + 4;
        const bool v0 = r0 < n_nodes;
        const bool v1 = r1 < n_nodes;
        // Clamp so loads are always in-bounds; store is predicated.
        const int c0 = v0 ? r0 : 0;
        const int c1 = v1 ? r1 : 0;

        const float4* x0 = reinterpret_cast<const float4*>(X + (size_t)c0 * N_FEAT);
        const float4* x1 = reinterpret_cast<const float4*>(X + (size_t)c1 * N_FEAT);

        float sum0 = 0.0f, sum1 = 0.0f;
        #pragma unroll
        for (int k4 = 0; k4 < N_FEAT / 4; ++k4) {
            // Warp-uniform addresses -> broadcast, one L1 wavefront each.
            const float4 a = x0[k4];
            const float4 b = x1[k4];
            sum0 = fmaf(a.x, w[4 * k4 + 0], sum0);
            sum1 = fmaf(b.x, w[4 * k4 + 0], sum1);
            sum0 = fmaf(a.y, w[4 * k4 + 1], sum0);
            sum1 = fmaf(b.y, w[4 * k4 + 1], sum1);
            sum0 = fmaf(a.z, w[4 * k4 + 2], sum0);
            sum1 = fmaf(b.z, w[4 * k4 + 2], sum1);
            sum0 = fmaf(a.w, w[4 * k4 + 3], sum0);
            sum1 = fmaf(b.w, w[4 * k4 + 3], sum1);
        }
        if (v0) g_h[(size_t)r0 * N_FEAT + col] = sum0;   // coalesced 256B/row-group
        if (v1) g_h[(size_t)r1 * N_FEAT + col] = sum1;
    }
}

// -----------------------------------------------------------------------------
// Kernel 2: edge scatter. 16 lanes per edge; each lane handles 4 channels via
// float4 gather from h and red.global.add.v4.f32 (no-return atomic) to out.
// Per edge: one coalesced 256B read + one coalesced 256B vector-reduction.
// L2-resident (h + out = 51 MB < 126 MB L2); near the LTS throughput cap.
// -----------------------------------------------------------------------------
__global__ void __launch_bounds__(256) scatter_edges_kernel(
    const float* __restrict__ edge_val,
    const int*   __restrict__ edge_src,
    const int*   __restrict__ edge_dst,
    float*       __restrict__ out,
    int n_edges)
{
    const int t    = blockIdx.x * blockDim.x + threadIdx.x;
    const int e    = t >> 4;          // edge index (16 lanes per edge)
    const int lane = t & 15;          // channel group 0..15 (4 floats each)
    if (e >= n_edges) return;

    // Edge metadata: uniform within each half-warp -> broadcast sectors.
    const int   s = edge_src[e];
    const int   d = edge_dst[e];
    const float v = edge_val[e];

    const float4 h = reinterpret_cast<const float4*>(g_h + (size_t)s * N_FEAT)[lane];
    const float mx = h.x * v, my = h.y * v, mz = h.z * v, mw = h.w * v;

    float* p = out + (size_t)d * N_FEAT + lane * 4;   // 16B-aligned
    asm volatile("red.global.add.v4.f32 [%0], {%1, %2, %3, %4};"
                 :: "l"(p), "f"(mx), "f"(my), "f"(mz), "f"(mw)
                 : "memory");
}

// -----------------------------------------------------------------------------
// Kernel 3: in-place ReLU epilogue over out (float4 vectorized).
// -----------------------------------------------------------------------------
__global__ void __launch_bounds__(256) relu_kernel(float* __restrict__ out, int n4)
{
    const int i = blockIdx.x * blockDim.x + threadIdx.x;
    if (i >= n4) return;
    float4 v = reinterpret_cast<float4*>(out)[i];
    v.x = fmaxf(v.x, 0.0f);
    v.y = fmaxf(v.y, 0.0f);
    v.z = fmaxf(v.z, 0.0f);
    v.w = fmaxf(v.w, 0.0f);
    reinterpret_cast<float4*>(out)[i] = v;
}

// -----------------------------------------------------------------------------
// Launch: memset(out) -> gemm -> scatter -> relu on the default stream,
// fully graph-capturable (memset node + kernel nodes only).
// Input order (metadata): X, W, edge_val, edge_src, edge_dst.
// -----------------------------------------------------------------------------
extern "C" void kernel_launch(void* const* d_in, const int* in_sizes, int n_in,
                              void* d_out, int out_size)
{
    const float* X        = (const float*)d_in[0];
    const float* W        = (const float*)d_in[1];
    const float* edge_val = (const float*)d_in[2];
    const int*   edge_src = (const int*)  d_in[3];
    const int*   edge_dst = (const int*)  d_in[4];
    float*       out      = (float*)d_out;

    const int n_nodes = in_sizes[0] / N_FEAT;   // 100000
    const int n_edges = in_sizes[2];            // 1600000

    // Zero the accumulation buffer (d_out is poisoned by the harness).
    cudaMemsetAsync(d_out, 0, (size_t)out_size * sizeof(float), 0);

    // 1) h = X @ W
    {
        int grid = (n_nodes + ROWS_PER_BLOCK - 1) / ROWS_PER_BLOCK;
        gemm_xw_kernel<<<grid, 256>>>(X, W, n_nodes);
    }

    // 2) scatter-add over edges (16 lanes per edge)
    {
        const long long total = (long long)n_edges * 16;
        int grid = (int)((total + 255) / 256);
        scatter_edges_kernel<<<grid, 256>>>(edge_val, edge_src, edge_dst,
                                            out, n_edges);
    }

    // 3) ReLU epilogue
    {
        const int n4 = (n_nodes * N_FEAT) / 4;
        int grid = (n4 + 255) / 256;
        relu_kernel<<<grid, 256>>>(out, n4);
    }
}

// round 7
// speedup vs baseline: 1.9139x; 1.9139x over previous
#include <cuda_runtime.h>
#include <cuda_bf16.h>
#include <cstdint>

// Problem constants (shapes fixed by the reference).
#define N_NODES 100000
#define N_FEAT  64        // both N_IN and N_OUT
#define TILE_ROWS 128     // rows per block in the GEMM

// Scratch for h = X @ W  (25.6 MB). __device__ global => allocation-free.
__device__ float g_h[(size_t)N_NODES * N_FEAT];

// -----------------------------------------------------------------------------
// Kernel 1: h = X @ W.  Smem-tiled, 8x4 register micro-tile per thread.
//   Block: 256 threads -> 128 rows x 64 cols.
//   thread: cg = tid&15 (cols cg*4..+3), rgrp = tid>>4 (rows rgrp*8..+7).
//   Lane layout => x-LDS broadcast (2 addrs/warp), w-LDS one 256B row: both
//   conflict-free with zero padding. 128 FMA per 12 LDS.128 => FMA-bound.
// -----------------------------------------------------------------------------
__global__ void __launch_bounds__(256) gemm_xw_kernel(
    const float* __restrict__ X, const float* __restrict__ W, int n_nodes)
{
    __shared__ float Xs[TILE_ROWS][N_FEAT];   // 32 KB, row-major (no transpose)
    __shared__ float Ws[N_FEAT][N_FEAT];      // 16 KB, row-major

    const int tid  = threadIdx.x;
    const int cg   = tid & 15;    // column group: cols cg*4 .. cg*4+3
    const int rgrp = tid >> 4;    // row group:    rows rgrp*8 .. rgrp*8+7
    const int base = blockIdx.x * TILE_ROWS;

    // ---- Load W (64x64 = 1024 float4), fully coalesced. ----
    {
        const float4* Wv  = reinterpret_cast<const float4*>(W);
        float4*       Wsv = reinterpret_cast<float4*>(Ws);
        #pragma unroll
        for (int i = 0; i < 4; ++i)
            Wsv[tid + i * 256] = Wv[tid + i * 256];
    }
    // ---- Load X tile (128x64 = 2048 float4), coalesced, row-clamped. ----
    {
        const float4* Xv  = reinterpret_cast<const float4*>(X);
        float4*       Xsv = reinterpret_cast<float4*>(Xs);
        #pragma unroll
        for (int i = 0; i < 8; ++i) {
            const int idx = tid + i * 256;            // float4 index in tile
            const int row = base + (idx >> 4);        // 16 float4 per row
            const int src = row < n_nodes ? row : (n_nodes - 1);  // clamp
            Xsv[idx] = Xv[(size_t)src * 16 + (idx & 15)];
        }
    }
    __syncthreads();

    float acc[8][4];
    #pragma unroll
    for (int i = 0; i < 8; ++i)
        #pragma unroll
        for (int c = 0; c < 4; ++c)
            acc[i][c] = 0.0f;

    // ---- Main loop over K in steps of 4. ----
    #pragma unroll 2
    for (int k4 = 0; k4 < N_FEAT / 4; ++k4) {
        // 4 W rows, this thread's 4 columns. One 256B row per warp: no conflicts.
        float4 wv[4];
        #pragma unroll
        for (int j = 0; j < 4; ++j)
            wv[j] = *reinterpret_cast<const float4*>(&Ws[k4 * 4 + j][cg * 4]);

        #pragma unroll
        for (int i = 0; i < 8; ++i) {
            // 2 distinct addresses per warp -> broadcast LDS.128.
            const float4 xv =
                *reinterpret_cast<const float4*>(&Xs[rgrp * 8 + i][k4 * 4]);
            #pragma unroll
            for (int c = 0; c < 4; ++c) {
                const float w0 = (&wv[0].x)[c];
                const float w1 = (&wv[1].x)[c];
                const float w2 = (&wv[2].x)[c];
                const float w3 = (&wv[3].x)[c];
                acc[i][c] = fmaf(xv.x, w0, acc[i][c]);
                acc[i][c] = fmaf(xv.y, w1, acc[i][c]);
                acc[i][c] = fmaf(xv.z, w2, acc[i][c]);
                acc[i][c] = fmaf(xv.w, w3, acc[i][c]);
            }
        }
    }

    // ---- Store: per rgrp-row, 16 lanes write consecutive 16B => coalesced. ----
    #pragma unroll
    for (int i = 0; i < 8; ++i) {
        const int row = base + rgrp * 8 + i;
        if (row < n_nodes) {
            float4 o;
            o.x = acc[i][0]; o.y = acc[i][1]; o.z = acc[i][2]; o.w = acc[i][3];
            *reinterpret_cast<float4*>(&g_h[(size_t)row * N_FEAT + cg * 4]) = o;
        }
    }
}

// -----------------------------------------------------------------------------
// Kernel 2: edge scatter. 16 lanes per edge; each lane handles 4 channels via
// float4 gather from h and red.global.add.v4.f32 (no-return atomic) to out.
// Per edge: one coalesced 256B read + one coalesced 256B vector-reduction.
// L2-resident (h + out = 51 MB < 126 MB L2); near the LTS throughput cap.
// -----------------------------------------------------------------------------
__global__ void __launch_bounds__(256) scatter_edges_kernel(
    const float* __restrict__ edge_val,
    const int*   __restrict__ edge_src,
    const int*   __restrict__ edge_dst,
    float*       __restrict__ out,
    int n_edges)
{
    const int t    = blockIdx.x * blockDim.x + threadIdx.x;
    const int e    = t >> 4;          // edge index (16 lanes per edge)
    const int lane = t & 15;          // channel group 0..15 (4 floats each)
    if (e >= n_edges) return;

    // Edge metadata: uniform within each half-warp -> broadcast sectors.
    const int   s = edge_src[e];
    const int   d = edge_dst[e];
    const float v = edge_val[e];

    const float4 h = reinterpret_cast<const float4*>(g_h + (size_t)s * N_FEAT)[lane];
    const float mx = h.x * v, my = h.y * v, mz = h.z * v, mw = h.w * v;

    float* p = out + (size_t)d * N_FEAT + lane * 4;   // 16B-aligned
    asm volatile("red.global.add.v4.f32 [%0], {%1, %2, %3, %4};"
                 :: "l"(p), "f"(mx), "f"(my), "f"(mz), "f"(mw)
                 : "memory");
}

// -----------------------------------------------------------------------------
// Kernel 3: in-place ReLU epilogue over out (float4 vectorized).
// -----------------------------------------------------------------------------
__global__ void __launch_bounds__(256) relu_kernel(float* __restrict__ out, int n4)
{
    const int i = blockIdx.x * blockDim.x + threadIdx.x;
    if (i >= n4) return;
    float4 v = reinterpret_cast<float4*>(out)[i];
    v.x = fmaxf(v.x, 0.0f);
    v.y = fmaxf(v.y, 0.0f);
    v.z = fmaxf(v.z, 0.0f);
    v.w = fmaxf(v.w, 0.0f);
    reinterpret_cast<float4*>(out)[i] = v;
}

// -----------------------------------------------------------------------------
// Launch: memset(out) -> gemm -> scatter -> relu on the default stream,
// fully graph-capturable (memset node + kernel nodes only).
// Input order (metadata): X, W, edge_val, edge_src, edge_dst.
// -----------------------------------------------------------------------------
extern "C" void kernel_launch(void* const* d_in, const int* in_sizes, int n_in,
                              void* d_out, int out_size)
{
    const float* X        = (const float*)d_in[0];
    const float* W        = (const float*)d_in[1];
    const float* edge_val = (const float*)d_in[2];
    const int*   edge_src = (const int*)  d_in[3];
    const int*   edge_dst = (const int*)  d_in[4];
    float*       out      = (float*)d_out;

    const int n_nodes = in_sizes[0] / N_FEAT;   // 100000
    const int n_edges = in_sizes[2];            // 1600000

    // Zero the accumulation buffer (d_out is poisoned by the harness).
    cudaMemsetAsync(d_out, 0, (size_t)out_size * sizeof(float), 0);

    // 1) h = X @ W
    {
        int grid = (n_nodes + TILE_ROWS - 1) / TILE_ROWS;
        gemm_xw_kernel<<<grid, 256>>>(X, W, n_nodes);
    }

    // 2) scatter-add over edges (16 lanes per edge)
    {
        const long long total = (long long)n_edges * 16;
        int grid = (int)((total + 255) / 256);
        scatter_edges_kernel<<<grid, 256>>>(edge_val, edge_src, edge_dst,
                                            out, n_edges);
    }

    // 3) ReLU epilogue
    {
        const int n4 = (n_nodes * N_FEAT) / 4;
        int grid = (n4 + 255) / 256;
        relu_kernel<<<grid, 256>>>(out, n4);
    }
}

// round 8
// speedup vs baseline: 2.2815x; 1.1921x over previous
#include <cuda_runtime.h>
#include <cuda_bf16.h>
#include <cstdint>

// Problem constants (shapes fixed by the reference).
#define N_NODES   100000
#define N_FEAT    64         // both N_IN and N_OUT
#define N_EDGES_MAX 1600000
#define TILE_ROWS 128        // rows per block in the GEMM
#define SCAN_TILE 1024       // elements per block in scan phase 1
#define NB_MAX    128        // max scan blocks (100000/1024 = 98)

// ---- Device-global scratch (allocation-free). ----
__device__ float g_h[(size_t)N_NODES * N_FEAT];       // h = X @ W (25.6 MB)
__device__ int   g_cnt[N_NODES];                      // per-dst degree
__device__ int   g_part[N_NODES];                     // block-local excl scan
__device__ int   g_bsums[NB_MAX];                     // scan block sums
__device__ int   g_row_start[N_NODES + 1];            // CSR row offsets
__device__ int   g_cursor[N_NODES];                   // fill cursors
__device__ int2  g_perm[N_EDGES_MAX];                 // packed {src, val_bits}

// -----------------------------------------------------------------------------
// GEMM: h = X @ W.  Smem-tiled, 8x4 register micro-tile per thread (R7 WIN).
// -----------------------------------------------------------------------------
__global__ void __launch_bounds__(256) gemm_xw_kernel(
    const float* __restrict__ X, const float* __restrict__ W, int n_nodes)
{
    __shared__ float Xs[TILE_ROWS][N_FEAT];   // 32 KB
    __shared__ float Ws[N_FEAT][N_FEAT];      // 16 KB

    const int tid  = threadIdx.x;
    const int cg   = tid & 15;    // cols cg*4 .. cg*4+3
    const int rgrp = tid >> 4;    // rows rgrp*8 .. rgrp*8+7
    const int base = blockIdx.x * TILE_ROWS;

    {
        const float4* Wv  = reinterpret_cast<const float4*>(W);
        float4*       Wsv = reinterpret_cast<float4*>(Ws);
        #pragma unroll
        for (int i = 0; i < 4; ++i)
            Wsv[tid + i * 256] = Wv[tid + i * 256];
    }
    {
        const float4* Xv  = reinterpret_cast<const float4*>(X);
        float4*       Xsv = reinterpret_cast<float4*>(Xs);
        #pragma unroll
        for (int i = 0; i < 8; ++i) {
            const int idx = tid + i * 256;
            const int row = base + (idx >> 4);
            const int src = row < n_nodes ? row : (n_nodes - 1);
            Xsv[idx] = Xv[(size_t)src * 16 + (idx & 15)];
        }
    }
    __syncthreads();

    float acc[8][4];
    #pragma unroll
    for (int i = 0; i < 8; ++i)
        #pragma unroll
        for (int c = 0; c < 4; ++c)
            acc[i][c] = 0.0f;

    #pragma unroll 2
    for (int k4 = 0; k4 < N_FEAT / 4; ++k4) {
        float4 wv[4];
        #pragma unroll
        for (int j = 0; j < 4; ++j)
            wv[j] = *reinterpret_cast<const float4*>(&Ws[k4 * 4 + j][cg * 4]);

        #pragma unroll
        for (int i = 0; i < 8; ++i) {
            const float4 xv =
                *reinterpret_cast<const float4*>(&Xs[rgrp * 8 + i][k4 * 4]);
            #pragma unroll
            for (int c = 0; c < 4; ++c) {
                acc[i][c] = fmaf(xv.x, (&wv[0].x)[c], acc[i][c]);
                acc[i][c] = fmaf(xv.y, (&wv[1].x)[c], acc[i][c]);
                acc[i][c] = fmaf(xv.z, (&wv[2].x)[c], acc[i][c]);
                acc[i][c] = fmaf(xv.w, (&wv[3].x)[c], acc[i][c]);
            }
        }
    }

    #pragma unroll
    for (int i = 0; i < 8; ++i) {
        const int row = base + rgrp * 8 + i;
        if (row < n_nodes) {
            float4 o;
            o.x = acc[i][0]; o.y = acc[i][1]; o.z = acc[i][2]; o.w = acc[i][3];
            *reinterpret_cast<float4*>(&g_h[(size_t)row * N_FEAT + cg * 4]) = o;
        }
    }
}

// -----------------------------------------------------------------------------
// CSR build phase 0: zero degree counters.
// -----------------------------------------------------------------------------
__global__ void zero_counts_kernel(int n)
{
    const int i = blockIdx.x * blockDim.x + threadIdx.x;
    if (i < n) g_cnt[i] = 0;
}

// -----------------------------------------------------------------------------
// CSR build phase 1: histogram of edge_dst (no-return atomics -> REDG).
// -----------------------------------------------------------------------------
__global__ void hist_kernel(const int* __restrict__ edge_dst, int n_edges)
{
    const int e = blockIdx.x * blockDim.x + threadIdx.x;
    if (e < n_edges) atomicAdd(&g_cnt[edge_dst[e]], 1);
}

// -----------------------------------------------------------------------------
// Scan phase 1: per-block (1024 elems) exclusive scan; emit block totals.
// -----------------------------------------------------------------------------
__global__ void __launch_bounds__(256) scan1_kernel(int n)
{
    __shared__ int warp_sums[8];
    const int tid  = threadIdx.x;
    const int lane = tid & 31;
    const int wid  = tid >> 5;
    const int base = blockIdx.x * SCAN_TILE + tid * 4;

    int v0 = (base + 0) < n ? g_cnt[base + 0] : 0;
    int v1 = (base + 1) < n ? g_cnt[base + 1] : 0;
    int v2 = (base + 2) < n ? g_cnt[base + 2] : 0;
    int v3 = (base + 3) < n ? g_cnt[base + 3] : 0;
    const int tsum = v0 + v1 + v2 + v3;

    // Inclusive warp scan of tsum.
    int x = tsum;
    #pragma unroll
    for (int o = 1; o < 32; o <<= 1) {
        int y = __shfl_up_sync(0xFFFFFFFFu, x, o);
        if (lane >= o) x += y;
    }
    if (lane == 31) warp_sums[wid] = x;
    __syncthreads();
    if (wid == 0) {
        int w = lane < 8 ? warp_sums[lane] : 0;
        #pragma unroll
        for (int o = 1; o < 8; o <<= 1) {
            int y = __shfl_up_sync(0xFFFFFFFFu, w, o);
            if (lane >= o) w += y;
        }
        if (lane < 8) warp_sums[lane] = w;
    }
    __syncthreads();

    int excl = x - tsum + (wid > 0 ? warp_sums[wid - 1] : 0);
    if ((base + 0) < n) g_part[base + 0] = excl; excl += v0;
    if ((base + 1) < n) g_part[base + 1] = excl; excl += v1;
    if ((base + 2) < n) g_part[base + 2] = excl; excl += v2;
    if ((base + 3) < n) g_part[base + 3] = excl;

    if (tid == 255) g_bsums[blockIdx.x] = warp_sums[7];   // block total
}

// -----------------------------------------------------------------------------
// Scan phase 2: single block, exclusive scan of block sums (nb <= 128).
// -----------------------------------------------------------------------------
__global__ void __launch_bounds__(128) scan2_kernel(int nb)
{
    __shared__ int sh[128];
    const int t = threadIdx.x;
    const int v = t < nb ? g_bsums[t] : 0;
    sh[t] = v;
    __syncthreads();
    #pragma unroll
    for (int o = 1; o < 128; o <<= 1) {
        const int y = (t >= o) ? sh[t - o] : 0;
        __syncthreads();
        sh[t] += y;
        __syncthreads();
    }
    if (t < nb) g_bsums[t] = sh[t] - v;   // exclusive
}

// -----------------------------------------------------------------------------
// Scan phase 3: row_start = part + block_offset; cursor = row_start.
// -----------------------------------------------------------------------------
__global__ void scan3_kernel(int n, int n_edges)
{
    const int i = blockIdx.x * blockDim.x + threadIdx.x;
    if (i < n) {
        const int rs = g_part[i] + g_bsums[i / SCAN_TILE];
        g_row_start[i] = rs;
        g_cursor[i]    = rs;
    }
    if (i == 0) g_row_start[n] = n_edges;
}

// -----------------------------------------------------------------------------
// CSR build phase 2: scatter edges into per-dst slots (counting sort).
// -----------------------------------------------------------------------------
__global__ void fill_kernel(const int*   __restrict__ edge_src,
                            const int*   __restrict__ edge_dst,
                            const float* __restrict__ edge_val,
                            int n_edges)
{
    const int e = blockIdx.x * blockDim.x + threadIdx.x;
    if (e >= n_edges) return;
    const int d   = edge_dst[e];
    const int pos = atomicAdd(&g_cursor[d], 1);
    int2 p;
    p.x = edge_src[e];
    p.y = __float_as_int(edge_val[e]);
    g_perm[pos] = p;
}

// -----------------------------------------------------------------------------
// Pull aggregation + fused ReLU. 16 lanes per node, 4 floats per lane.
// Per edge: 8B meta broadcast + 256B read-only gather of h[src]. No atomics,
// no separate memset/relu passes.
// -----------------------------------------------------------------------------
__global__ void __launch_bounds__(256) aggregate_kernel(
    float* __restrict__ out, int n_nodes)
{
    const int t    = blockIdx.x * blockDim.x + threadIdx.x;
    const int node = t >> 4;
    const int lane = t & 15;
    if (node >= n_nodes) return;

    const int start = g_row_start[node];
    const int end   = g_row_start[node + 1];
    const float4* Hv = reinterpret_cast<const float4*>(g_h);

    float4 acc = make_float4(0.0f, 0.0f, 0.0f, 0.0f);

    int e = start;
    for (; e + 1 < end; e += 2) {                 // 2-way for MLP
        const int2 p0 = g_perm[e];
        const int2 p1 = g_perm[e + 1];
        const float4 h0 = Hv[(size_t)p0.x * 16 + lane];
        const float4 h1 = Hv[(size_t)p1.x * 16 + lane];
        const float v0 = __int_as_float(p0.y);
        const float v1 = __int_as_float(p1.y);
        acc.x = fmaf(h0.x, v0, acc.x);  acc.y = fmaf(h0.y, v0, acc.y);
        acc.z = fmaf(h0.z, v0, acc.z);  acc.w = fmaf(h0.w, v0, acc.w);
        acc.x = fmaf(h1.x, v1, acc.x);  acc.y = fmaf(h1.y, v1, acc.y);
        acc.z = fmaf(h1.z, v1, acc.z);  acc.w = fmaf(h1.w, v1, acc.w);
    }
    if (e < end) {
        const int2 p = g_perm[e];
        const float4 h = Hv[(size_t)p.x * 16 + lane];
        const float v = __int_as_float(p.y);
        acc.x = fmaf(h.x, v, acc.x);  acc.y = fmaf(h.y, v, acc.y);
        acc.z = fmaf(h.z, v, acc.z);  acc.w = fmaf(h.w, v, acc.w);
    }

    acc.x = fmaxf(acc.x, 0.0f);
    acc.y = fmaxf(acc.y, 0.0f);
    acc.z = fmaxf(acc.z, 0.0f);
    acc.w = fmaxf(acc.w, 0.0f);
    reinterpret_cast<float4*>(out)[(size_t)node * 16 + lane] = acc;
}

// -----------------------------------------------------------------------------
// Launch: CSR build + gemm + pull-aggregate, single stream, graph-capturable
// (kernel nodes only).  Input order: X, W, edge_val, edge_src, edge_dst.
// -----------------------------------------------------------------------------
extern "C" void kernel_launch(void* const* d_in, const int* in_sizes, int n_in,
                              void* d_out, int out_size)
{
    const float* X        = (const float*)d_in[0];
    const float* W        = (const float*)d_in[1];
    const float* edge_val = (const float*)d_in[2];
    const int*   edge_src = (const int*)  d_in[3];
    const int*   edge_dst = (const int*)  d_in[4];
    float*       out      = (float*)d_out;

    const int n_nodes = in_sizes[0] / N_FEAT;   // 100000
    const int n_edges = in_sizes[2];            // 1600000
    const int nb      = (n_nodes + SCAN_TILE - 1) / SCAN_TILE;   // 98

    const int gN = (n_nodes + 255) / 256;       // node-sized grids
    const int gE = (n_edges + 255) / 256;       // edge-sized grids

    // CSR-by-dst build (counting sort).
    zero_counts_kernel<<<gN, 256>>>(n_nodes);
    hist_kernel<<<gE, 256>>>(edge_dst, n_edges);
    scan1_kernel<<<nb, 256>>>(n_nodes);
    scan2_kernel<<<1, 128>>>(nb);
    scan3_kernel<<<gN, 256>>>(n_nodes, n_edges);
    fill_kernel<<<gE, 256>>>(edge_src, edge_dst, edge_val, n_edges);

    // h = X @ W  (independent of CSR build; sequenced on the same stream).
    gemm_xw_kernel<<<(n_nodes + TILE_ROWS - 1) / TILE_ROWS, 256>>>(X, W, n_nodes);

    // out = relu(A @ h), pull-style, fused ReLU.
    {
        const long long total = (long long)n_nodes * 16;
        const int grid = (int)((total + 255) / 256);
        aggregate_kernel<<<grid, 256>>>(out, n_nodes);
    }
}

// round 12
// speedup vs baseline: 2.6027x; 1.1408x over previous
#include <cuda_runtime.h>
#include <cuda_fp16.h>
#include <cstdint>

// Problem constants (shapes fixed by the reference).
#define N_NODES   100000
#define N_FEAT    64         // both N_IN and N_OUT
#define N_EDGES_MAX 1600000
#define TILE_ROWS 128        // rows per block in the GEMM
#define SCAN_TILE 1024       // nodes per block in scan phase 1/3
#define NB_MAX    128

// ---- Device-global scratch (allocation-free; zero-initialized at load). ----
__device__ __half g_h[(size_t)N_NODES * N_FEAT];     // h = X@W in fp16 (12.8 MB)
__device__ int    g_cnt[N_NODES];                    // per-dst degree (starts 0;
                                                     // re-zeroed by aggregate)
__device__ int    g_part[N_NODES];                   // block-local excl scan
__device__ int    g_bsums[NB_MAX];                   // scan-tile totals
__device__ int    g_row_start[N_NODES + 1];          // CSR row offsets
__device__ int    g_cursor[N_NODES];                 // fill cursors
__device__ int2   g_perm[N_EDGES_MAX];               // packed {src, val_bits}

// -----------------------------------------------------------------------------
// 1) Histogram of edge_dst. g_cnt is zero on entry (zero-init / re-zeroed by
//    the aggregate kernel at the end of every execution).
// -----------------------------------------------------------------------------
__global__ void hist_kernel(const int* __restrict__ edge_dst, int n_edges)
{
    const int e = blockIdx.x * blockDim.x + threadIdx.x;
    if (e < n_edges) atomicAdd(&g_cnt[edge_dst[e]], 1);
}

// -----------------------------------------------------------------------------
// 2) Per-tile (1024 nodes) exclusive scan of g_cnt; emit tile totals.
// -----------------------------------------------------------------------------
__global__ void __launch_bounds__(256) scan1_kernel(int n)
{
    __shared__ int warp_sums[8];
    const int tid  = threadIdx.x;
    const int lane = tid & 31;
    const int wid  = tid >> 5;
    const int base = blockIdx.x * SCAN_TILE + tid * 4;

    int v0 = (base + 0) < n ? g_cnt[base + 0] : 0;
    int v1 = (base + 1) < n ? g_cnt[base + 1] : 0;
    int v2 = (base + 2) < n ? g_cnt[base + 2] : 0;
    int v3 = (base + 3) < n ? g_cnt[base + 3] : 0;
    const int tsum = v0 + v1 + v2 + v3;

    int x = tsum;                               // inclusive warp scan
    #pragma unroll
    for (int o = 1; o < 32; o <<= 1) {
        int y = __shfl_up_sync(0xFFFFFFFFu, x, o);
        if (lane >= o) x += y;
    }
    if (lane == 31) warp_sums[wid] = x;
    __syncthreads();
    if (wid == 0) {
        int w = lane < 8 ? warp_sums[lane] : 0;
        #pragma unroll
        for (int o = 1; o < 8; o <<= 1) {
            int y = __shfl_up_sync(0xFFFFFFFFu, w, o);
            if (lane >= o) w += y;
        }
        if (lane < 8) warp_sums[lane] = w;
    }
    __syncthreads();

    int excl = x - tsum + (wid > 0 ? warp_sums[wid - 1] : 0);
    if ((base + 0) < n) g_part[base + 0] = excl; excl += v0;
    if ((base + 1) < n) g_part[base + 1] = excl; excl += v1;
    if ((base + 2) < n) g_part[base + 2] = excl; excl += v2;
    if ((base + 3) < n) g_part[base + 3] = excl;

    if (tid == 255) g_bsums[blockIdx.x] = warp_sums[7];   // tile total
}

// -----------------------------------------------------------------------------
// 3) row_start = part + prefix(bsums);  cursor = row_start.
//    Each block computes its own bsums prefix (<=128 L2-hit loads) -- no
//    separate scan2 launch.
// -----------------------------------------------------------------------------
__global__ void __launch_bounds__(256) scan3_kernel(int n, int n_edges)
{
    __shared__ int warp_sums[8];
    __shared__ int s_pref;
    const int t = threadIdx.x;

    int v = (t < (int)blockIdx.x) ? g_bsums[t] : 0;     // blockIdx.x < NB_MAX
    #pragma unroll
    for (int o = 16; o; o >>= 1) v += __shfl_down_sync(0xFFFFFFFFu, v, o);
    if ((t & 31) == 0) warp_sums[t >> 5] = v;
    __syncthreads();
    if (t == 0) {
        int s = 0;
        #pragma unroll
        for (int w = 0; w < 8; ++w) s += warp_sums[w];
        s_pref = s;
    }
    __syncthreads();
    const int pref = s_pref;

    #pragma unroll
    for (int k = 0; k < 4; ++k) {
        const int i = blockIdx.x * SCAN_TILE + k * 256 + t;
        if (i < n) {
            const int rs = g_part[i] + pref;
            g_row_start[i] = rs;
            g_cursor[i]    = rs;
        }
    }
    if (blockIdx.x == 0 && t == 0) g_row_start[n] = n_edges;
}

// -----------------------------------------------------------------------------
// 4) FUSED: gemm (blocks [0, g_gemm)) + edge fill (remaining blocks).
//    The two halves are independent; fill's ATOMG latency overlaps gemm's FMA.
// -----------------------------------------------------------------------------
__global__ void __launch_bounds__(256) gemm_fill_kernel(
    const float* __restrict__ X, const float* __restrict__ W,
    const int*   __restrict__ edge_src,
    const int*   __restrict__ edge_dst,
    const float* __restrict__ edge_val,
    int n_nodes, int n_edges, int g_gemm)
{
    __shared__ float Xs[TILE_ROWS][N_FEAT];   // 32 KB (gemm path only)
    __shared__ float Ws[N_FEAT][N_FEAT];      // 16 KB

    if ((int)blockIdx.x >= g_gemm) {
        // ---- fill path: counting-sort edges into per-dst CSR slots ----
        const int e = (blockIdx.x - g_gemm) * 256 + threadIdx.x;
        if (e < n_edges) {
            const int d   = edge_dst[e];
            const int pos = atomicAdd(&g_cursor[d], 1);
            g_perm[pos] = make_int2(edge_src[e], __float_as_int(edge_val[e]));
        }
        return;
    }

    // ---- gemm path: h = X @ W (R7 tiling), fp16 store ----
    const int tid  = threadIdx.x;
    const int cg   = tid & 15;    // cols cg*4 .. cg*4+3
    const int rgrp = tid >> 4;    // rows rgrp*8 .. rgrp*8+7
    const int base = blockIdx.x * TILE_ROWS;

    {
        const float4* Wv  = reinterpret_cast<const float4*>(W);
        float4*       Wsv = reinterpret_cast<float4*>(Ws);
        #pragma unroll
        for (int i = 0; i < 4; ++i)
            Wsv[tid + i * 256] = Wv[tid + i * 256];
    }
    {
        const float4* Xv  = reinterpret_cast<const float4*>(X);
        float4*       Xsv = reinterpret_cast<float4*>(Xs);
        #pragma unroll
        for (int i = 0; i < 8; ++i) {
            const int idx = tid + i * 256;
            const int row = base + (idx >> 4);
            const int src = row < n_nodes ? row : (n_nodes - 1);
            Xsv[idx] = Xv[(size_t)src * 16 + (idx & 15)];
        }
    }
    __syncthreads();

    float acc[8][4];
    #pragma unroll
    for (int i = 0; i < 8; ++i)
        #pragma unroll
        for (int c = 0; c < 4; ++c)
            acc[i][c] = 0.0f;

    #pragma unroll 2
    for (int k4 = 0; k4 < N_FEAT / 4; ++k4) {
        float4 wv[4];
        #pragma unroll
        for (int j = 0; j < 4; ++j)
            wv[j] = *reinterpret_cast<const float4*>(&Ws[k4 * 4 + j][cg * 4]);

        #pragma unroll
        for (int i = 0; i < 8; ++i) {
            const float4 xv =
                *reinterpret_cast<const float4*>(&Xs[rgrp * 8 + i][k4 * 4]);
            #pragma unroll
            for (int c = 0; c < 4; ++c) {
                acc[i][c] = fmaf(xv.x, (&wv[0].x)[c], acc[i][c]);
                acc[i][c] = fmaf(xv.y, (&wv[1].x)[c], acc[i][c]);
                acc[i][c] = fmaf(xv.z, (&wv[2].x)[c], acc[i][c]);
                acc[i][c] = fmaf(xv.w, (&wv[3].x)[c], acc[i][c]);
            }
        }
    }

    // fp16 store: 4 cols -> 2x half2 = 8B per row; 16 lanes = 128B coalesced.
    #pragma unroll
    for (int i = 0; i < 8; ++i) {
        const int row = base + rgrp * 8 + i;
        if (row < n_nodes) {
            const __half2 h01 = __floats2half2_rn(acc[i][0], acc[i][1]);
            const __half2 h23 = __floats2half2_rn(acc[i][2], acc[i][3]);
            uint2 o;
            o.x = *reinterpret_cast<const unsigned*>(&h01);
            o.y = *reinterpret_cast<const unsigned*>(&h23);
            reinterpret_cast<uint2*>(g_h)[(size_t)row * 16 + cg] = o;
        }
    }
}

// -----------------------------------------------------------------------------
// 5) Pull aggregation + fused ReLU. 16 lanes per node; each lane gathers 8B
//    (4 halves) per edge, accumulates in fp32, writes 16B of out.
//    Also re-zeros g_cnt[node] so the next execution's histogram starts clean.
// -----------------------------------------------------------------------------
__global__ void __launch_bounds__(256) aggregate_kernel(
    float* __restrict__ out, int n_nodes)
{
    const int t    = blockIdx.x * blockDim.x + threadIdx.x;
    const int node = t >> 4;
    const int lane = t & 15;
    if (node >= n_nodes) return;

    if (lane == 0) g_cnt[node] = 0;     // restore invariant for next execution

    const int start = g_row_start[node];
    const int end   = g_row_start[node + 1];
    const uint2* Hv = reinterpret_cast<const uint2*>(g_h);   // 4 halves per uint2

    float4 acc = make_float4(0.0f, 0.0f, 0.0f, 0.0f);

    int e = start;
    for (; e + 1 < end; e += 2) {                 // 2-way for MLP
        const int2 p0 = g_perm[e];
        const int2 p1 = g_perm[e + 1];
        const uint2 q0 = Hv[(size_t)p0.x * 16 + lane];
        const uint2 q1 = Hv[(size_t)p1.x * 16 + lane];
        const float v0 = __int_as_float(p0.y);
        const float v1 = __int_as_float(p1.y);
        const float2 a0 = __half22float2(*reinterpret_cast<const __half2*>(&q0.x));
        const float2 a1 = __half22float2(*reinterpret_cast<const __half2*>(&q0.y));
        const float2 b0 = __half22float2(*reinterpret_cast<const __half2*>(&q1.x));
        const float2 b1 = __half22float2(*reinterpret_cast<const __half2*>(&q1.y));
        acc.x = fmaf(a0.x, v0, acc.x);  acc.y = fmaf(a0.y, v0, acc.y);
        acc.z = fmaf(a1.x, v0, acc.z);  acc.w = fmaf(a1.y, v0, acc.w);
        acc.x = fmaf(b0.x, v1, acc.x);  acc.y = fmaf(b0.y, v1, acc.y);
        acc.z = fmaf(b1.x, v1, acc.z);  acc.w = fmaf(b1.y, v1, acc.w);
    }
    if (e < end) {
        const int2 p = g_perm[e];
        const uint2 q = Hv[(size_t)p.x * 16 + lane];
        const float v = __int_as_float(p.y);
        const float2 a0 = __half22float2(*reinterpret_cast<const __half2*>(&q.x));
        const float2 a1 = __half22float2(*reinterpret_cast<const __half2*>(&q.y));
        acc.x = fmaf(a0.x, v, acc.x);  acc.y = fmaf(a0.y, v, acc.y);
        acc.z = fmaf(a1.x, v, acc.z);  acc.w = fmaf(a1.y, v, acc.w);
    }

    acc.x = fmaxf(acc.x, 0.0f);
    acc.y = fmaxf(acc.y, 0.0f);
    acc.z = fmaxf(acc.z, 0.0f);
    acc.w = fmaxf(acc.w, 0.0f);
    reinterpret_cast<float4*>(out)[(size_t)node * 16 + lane] = acc;
}

// -----------------------------------------------------------------------------
// Launch: hist -> scan1 -> scan3 -> fused(gemm+fill) -> aggregate.
// 5 kernel launches, single stream, graph-capturable.
// Input order (metadata): X, W, edge_val, edge_src, edge_dst.
// -----------------------------------------------------------------------------
extern "C" void kernel_launch(void* const* d_in, const int* in_sizes, int n_in,
                              void* d_out, int out_size)
{
    const float* X        = (const float*)d_in[0];
    const float* W        = (const float*)d_in[1];
    const float* edge_val = (const float*)d_in[2];
    const int*   edge_src = (const int*)  d_in[3];
    const int*   edge_dst = (const int*)  d_in[4];
    float*       out      = (float*)d_out;

    const int n_nodes = in_sizes[0] / N_FEAT;   // 100000
    const int n_edges = in_sizes[2];            // 1600000
    const int nb      = (n_nodes + SCAN_TILE - 1) / SCAN_TILE;   // 98
    const int gE      = (n_edges + 255) / 256;                   // 6250
    const int gGemm   = (n_nodes + TILE_ROWS - 1) / TILE_ROWS;   // 782

    hist_kernel<<<gE, 256>>>(edge_dst, n_edges);
    scan1_kernel<<<nb, 256>>>(n_nodes);
    scan3_kernel<<<nb, 256>>>(n_nodes, n_edges);
    gemm_fill_kernel<<<gGemm + gE, 256>>>(X, W, edge_src, edge_dst, edge_val,
                                          n_nodes, n_edges, gGemm);
    {
        const long long total = (long long)n_nodes * 16;
        const int grid = (int)((total + 255) / 256);
        aggregate_kernel<<<grid, 256>>>(out, n_nodes);
    }
}